// round 6
// baseline (speedup 1.0000x reference)
#include <cuda_runtime.h>
#include <cuda_bf16.h>

// Problem constants (fixed by the reference)
#define Cc    8
#define Ll    4096
#define Ff    32
#define Kk    10
#define PROC  20
#define STEP  5
#define NWIN  815          // == CHAN_OUT, no pad region
#define WPB   128          // windows per block (smaller blocks -> finer residency)
#define NTILE 7            // ceil(815/128) -> covers 896 windows

// Shared x tile: covers WPB windows -> WPB*STEP + (PROC-STEP) = 655 floats
#define SXN (WPB * STEP + PROC - STEP)

__global__ __launch_bounds__(WPB, 7)
void dtw_kernel(const float* __restrict__ x,
                const float* __restrict__ kernels,
                float* __restrict__ out)
{
    const int tile = blockIdx.x;          // window tile [0, NTILE)
    const int f    = blockIdx.y;          // filter     [0, Ff)
    const int bc   = blockIdx.z;          // b*C + c    [0, 64)
    const int tid  = threadIdx.x;

    __shared__ float sx[SXN];

    // Cooperative, coalesced load of the x tile for this (b,c)
    const int    base = tile * WPB * STEP;
    const float* xc   = x + (size_t)bc * Ll;
    #pragma unroll
    for (int i = tid; i < SXN; i += WPB) {
        int g = base + i;
        sx[i] = (g < Ll) ? xc[g] : 0.0f;
    }
    __syncthreads();

    // Early-exit: lanes without a real window skip ALL compute.
    // (No syncs below this point, so divergence-safe.)
    const int wg = tile * WPB + tid;
    if (wg >= NWIN) return;

    // Kernel taps: warp-uniform addresses -> broadcast loads, L1-resident
    float ker[Kk];
    #pragma unroll
    for (int i = 0; i < Kk; i++) ker[i] = __ldg(&kernels[f * Kk + i]);

    // Window: stride-5 shared reads, gcd(5,32)=1 -> conflict-free
    float w[PROC];
    #pragma unroll
    for (int j = 0; j < PROC; j++) w[j] = sx[tid * STEP + j];

    // DTW table, row-sweep with register-resident row of length PROC.
    // Everything fully unrolled: register renaming kills all rotation MOVs.
    float acc[PROC];

    // Row 0: cumulative sum of squared diffs
    {
        const float k0 = ker[0];
        float d = k0 - w[0];
        acc[0] = d * d;
        #pragma unroll
        for (int j = 1; j < PROC; j++) {
            d = k0 - w[j];
            acc[j] = fmaf(d, d, acc[j - 1]);
        }
    }

    // Rows 1..K-1, fully unrolled. Reassociated min: pmin = min(up, diag)
    // is off the left-dependency chain -> serial path = FMNMX + FFMA (~10 cyc).
    #pragma unroll
    for (int i = 1; i < Kk; i++) {
        const float kv = ker[i];
        float diag = acc[0];              // old prev[0]
        float d = kv - w[0];
        acc[0] = fmaf(d, d, acc[0]);      // new[0] = d + prev[0]
        #pragma unroll
        for (int j = 1; j < PROC; j++) {
            const float up   = acc[j];            // prev[j]
            const float pmin = fminf(up, diag);   // independent of the chain
            const float m    = fminf(acc[j - 1], pmin);
            d = kv - w[j];
            acc[j] = fmaf(d, d, m);
            diag = up;                            // renamed away by unroll
        }
    }

    // out[b, c*F + f, w]: coalesced in w
    out[((size_t)bc * Ff + f) * NWIN + wg] = acc[PROC - 1];
}

extern "C" void kernel_launch(void* const* d_in, const int* in_sizes, int n_in,
                              void* d_out, int out_size)
{
    const float* x       = (const float*)d_in[0];   // (8, 8, 4096) f32
    const float* kernels = (const float*)d_in[1];   // (32, 10) f32
    float*       out     = (float*)d_out;           // (8, 256, 815) f32

    (void)in_sizes; (void)n_in; (void)out_size;

    dim3 grid(NTILE, Ff, 8 * Cc);   // (7, 32, 64)
    dtw_kernel<<<grid, WPB>>>(x, kernels, out);
}

// round 7
// speedup vs baseline: 1.6507x; 1.6507x over previous
#include <cuda_runtime.h>
#include <cuda_bf16.h>

// Problem constants (fixed by the reference)
#define Cc    8
#define Ll    4096
#define Ff    32
#define Kk    10
#define PROC  20
#define STEP  5
#define NWIN  815          // == CHAN_OUT, no pad region
#define WPB   256          // threads per block
#define WINPB 512          // windows per block (2 per thread, adjacent)
#define NTILE 2            // ceil(815/512)

// Shared x tile: covers WINPB windows -> WINPB*STEP + (PROC-STEP) = 2575 floats
#define SXN (WINPB * STEP + PROC - STEP)

__global__ __launch_bounds__(WPB, 2)
void dtw_kernel(const float* __restrict__ x,
                const float* __restrict__ kernels,
                float* __restrict__ out)
{
    const int tile = blockIdx.x;          // window tile [0, NTILE)
    const int f    = blockIdx.y;          // filter     [0, Ff)
    const int bc   = blockIdx.z;          // b*C + c    [0, 64)
    const int tid  = threadIdx.x;

    __shared__ float sx[SXN];

    // Cooperative, coalesced load of the x tile for this (b,c)
    const int    base = tile * WINPB * STEP;
    const float* xc   = x + (size_t)bc * Ll;
    #pragma unroll
    for (int i = tid; i < SXN; i += WPB) {
        int g = base + i;
        sx[i] = (g < Ll) ? xc[g] : 0.0f;
    }
    __syncthreads();

    // This thread owns adjacent windows g0 = tile*512 + 2*tid and g0+1.
    const int g0 = tile * WINPB + 2 * tid;
    if (g0 >= NWIN) return;               // no syncs below: divergence-safe

    // Kernel taps: warp-uniform addresses -> broadcast loads, L1-resident
    float ker[Kk];
    #pragma unroll
    for (int i = 0; i < Kk; i++) ker[i] = __ldg(&kernels[f * Kk + i]);

    // 25-float span covers BOTH windows: w0[j] = s[j], w1[j] = s[j+5].
    // (Adjacent windows overlap in 15 samples -> 25 regs instead of 40.)
    float s[PROC + STEP];
    #pragma unroll
    for (int j = 0; j < PROC + STEP; j++) s[j] = sx[2 * tid * STEP + j];

    // Two independent DTW tables, interleaved for ILP=2. Fully unrolled:
    // register renaming kills all rotation MOVs (R3/R4 lesson).
    float a0[PROC], a1[PROC];

    // Row 0: cumulative sum of squared diffs
    {
        const float k0 = ker[0];
        float d0 = k0 - s[0];
        float d1 = k0 - s[STEP];
        a0[0] = d0 * d0;
        a1[0] = d1 * d1;
        #pragma unroll
        for (int j = 1; j < PROC; j++) {
            d0 = k0 - s[j];
            d1 = k0 - s[j + STEP];
            a0[j] = fmaf(d0, d0, a0[j - 1]);
            a1[j] = fmaf(d1, d1, a1[j - 1]);
        }
    }

    // Rows 1..K-1. Reassociated min keeps pmin off the left-dependency chain:
    // serial path per cell = FMNMX + FFMA; two chains overlap across windows.
    #pragma unroll
    for (int i = 1; i < Kk; i++) {
        const float kv = ker[i];
        float dg0 = a0[0];
        float dg1 = a1[0];
        float d0 = kv - s[0];
        float d1 = kv - s[STEP];
        a0[0] = fmaf(d0, d0, a0[0]);
        a1[0] = fmaf(d1, d1, a1[0]);
        #pragma unroll
        for (int j = 1; j < PROC; j++) {
            const float up0 = a0[j];
            const float up1 = a1[j];
            const float p0  = fminf(up0, dg0);    // off-chain
            const float p1  = fminf(up1, dg1);
            const float m0  = fminf(a0[j - 1], p0);
            const float m1  = fminf(a1[j - 1], p1);
            d0 = kv - s[j];
            d1 = kv - s[j + STEP];
            a0[j] = fmaf(d0, d0, m0);
            a1[j] = fmaf(d1, d1, m1);
            dg0 = up0;                            // renamed away by unroll
            dg1 = up1;
        }
    }

    // out[b, c*F + f, w]: coalesced in w (two adjacent elements per thread)
    const size_t o = ((size_t)bc * Ff + f) * NWIN + g0;
    out[o] = a0[PROC - 1];
    if (g0 + 1 < NWIN) out[o + 1] = a1[PROC - 1];
}

extern "C" void kernel_launch(void* const* d_in, const int* in_sizes, int n_in,
                              void* d_out, int out_size)
{
    const float* x       = (const float*)d_in[0];   // (8, 8, 4096) f32
    const float* kernels = (const float*)d_in[1];   // (32, 10) f32
    float*       out     = (float*)d_out;           // (8, 256, 815) f32

    (void)in_sizes; (void)n_in; (void)out_size;

    dim3 grid(NTILE, Ff, 8 * Cc);   // (2, 32, 64)
    dtw_kernel<<<grid, WPB>>>(x, kernels, out);
}